// round 13
// baseline (speedup 1.0000x reference)
#include <cuda_runtime.h>

#define NBLK 288
#define NTHR 640

// Staged partial batch-sums of x: [z=16][i*1152+c]  (590 KB)
__device__ float g_part[16 * 9216];
// Monotonic grid-barrier counter (epoch-safe across graph replays).
__device__ unsigned g_bar;

__global__ void __launch_bounds__(NTHR, 2) mono_kernel(const float* __restrict__ x,
                                                       const float* __restrict__ W,
                                                       float* __restrict__ out) {
    const int t = threadIdx.x;            // 0..639
    const int blk = blockIdx.x;           // 0..287
    const int c0 = blk * 4;               // 4 capsules per block

    __shared__ float4 sm_ph1[512];        // phase-1 partials (8 KB)
    __shared__ float sm_part[512];        // phase-2 xs partials
    __shared__ float sm_xs[32];           // [lc*8 + i]
    __shared__ float sm_usq[40];
    __shared__ float sm_b[40];
    __shared__ float sm_e[40];
    __shared__ float sm_k[40];

    // ── W stream into flight first (2 coalesced LDG.128 / thread) ──
    const size_t e = (size_t)blk * NTHR + t;        // element c*160 + u*16 + s
    const float4* wp = reinterpret_cast<const float4*>(W) + e * 2;
    const float4 w0 = __ldg(wp);
    const float4 w1 = __ldg(wp + 1);

    // ── Phase 1: this block's slice of the x batch-reduction ──
    // Output o = z*2304 + col (float4 cols); 128 outputs/block, 4 threads each
    // summing 4 batches (coalesced 128B segments per warp).
    const int z = blk / 18;                          // 0..15
    const int colbase = (blk % 18) * 128;
    if (t < 512) {
        const int col = colbase + (t >> 2);
        const int j = t & 3;
        const float4* p = reinterpret_cast<const float4*>(x)
                        + (size_t)(z * 16 + j * 4) * 2304 + col;
        const float4 a0 = __ldg(p);
        const float4 a1 = __ldg(p + 2304);
        const float4 a2 = __ldg(p + 2 * 2304);
        const float4 a3 = __ldg(p + 3 * 2304);
        float4 s;
        s.x = (a0.x + a1.x) + (a2.x + a3.x);
        s.y = (a0.y + a1.y) + (a2.y + a3.y);
        s.z = (a0.z + a1.z) + (a2.z + a3.z);
        s.w = (a0.w + a1.w) + (a2.w + a3.w);
        sm_ph1[t] = s;
    }
    __syncthreads();
    if (t < 128) {
        const float4 s0 = sm_ph1[t * 4], s1 = sm_ph1[t * 4 + 1];
        const float4 s2 = sm_ph1[t * 4 + 2], s3 = sm_ph1[t * 4 + 3];
        float4 s;
        s.x = (s0.x + s1.x) + (s2.x + s3.x);
        s.y = (s0.y + s1.y) + (s2.y + s3.y);
        s.z = (s0.z + s1.z) + (s2.z + s3.z);
        s.w = (s0.w + s1.w) + (s2.w + s3.w);
        reinterpret_cast<float4*>(g_part)[(size_t)z * 2304 + colbase + t] = s;
    }

    // ── Grid barrier (spin; all 288 blocks are co-resident by construction) ──
    __threadfence();
    __syncthreads();
    if (t == 0) {
        const unsigned old = atomicAdd(&g_bar, 1u);
        const unsigned target = old - (old % NBLK) + NBLK;   // this replay's epoch
        volatile unsigned* vb = &g_bar;
        while (*vb < target) { }
        __threadfence();
    }
    __syncthreads();

    // ── Phase 2: xs gather (g_part is L2-hot), one load per thread ──
    if (t < 512) {
        const int v = t & 31;                        // (lc, i)
        const int cc = c0 + (v >> 3);
        const int i = v & 7;
        sm_part[t] = g_part[(size_t)(t >> 5) * 9216 + i * 1152 + cc];
    }
    __syncthreads();
    if (t < 32) {
        float a = 0.f;
        #pragma unroll
        for (int ch = 0; ch < 16; ++ch) a += sm_part[ch * 32 + t];
        sm_xs[t] = a;
    }
    __syncthreads();

    // us = dot(W row, xs) for this element
    const int lc = t / 160;                          // 0..3
    const int r = t - lc * 160;                      // u*16 + s
    const int u = r >> 4;
    const float* xp = sm_xs + lc * 8;
    const float us = w0.x * xp[0] + w0.y * xp[1] + w0.z * xp[2] + w0.w * xp[3]
                   + w1.x * xp[4] + w1.y * xp[5] + w1.z * xp[6] + w1.w * xp[7];

    // ||u_sum||^2 over the 16 s-lanes of this (c,u) group
    float q = us * us;
    q += __shfl_xor_sync(0xffffffffu, q, 1);
    q += __shfl_xor_sync(0xffffffffu, q, 2);
    q += __shfl_xor_sync(0xffffffffu, q, 4);
    q += __shfl_xor_sync(0xffffffffu, q, 8);
    if ((t & 15) == 0) sm_usq[lc * 10 + u] = q;
    __syncthreads();

    // ── Scalar routing on threads t<40 (t = cc*10 + uu); block-level syncs ──
    {
        const bool act = (t < 40);
        const int cc = act ? (t / 10) : 0;
        const float usq = act ? sm_usq[t] : 0.f;
        float b = 0.f, cij = 0.1f, k = 0.f;          // softmax(0)=1/10 exact

        #pragma unroll
        for (int it = 0; it < 3; ++it) {
            const float msq = cij * cij * usq;
            const float coef = msq / (1.0f + msq) * rsqrtf(msq);
            k = coef * cij;

            if (it < 2) {
                if (act) { b += k * usq * (1.0f / 256.0f); sm_b[t] = b; }
                __syncthreads();
                float ex = 0.f;
                if (act) {
                    const float* bb = sm_b + cc * 10;
                    float m = bb[0];
                    #pragma unroll
                    for (int j = 1; j < 10; ++j) m = fmaxf(m, bb[j]);
                    ex = __expf(b - m);
                    sm_e[t] = ex;
                }
                __syncthreads();
                if (act) {
                    const float* ep = sm_e + cc * 10;
                    float d = ep[0];
                    #pragma unroll
                    for (int j = 1; j < 10; ++j) d += ep[j];
                    cij = ex / d;
                }
            }
        }
        if (act) sm_k[t] = k;
    }
    __syncthreads();

    // Final scale; coalesced 4B stores.
    out[e] = sm_k[lc * 10 + u] * us;
}

extern "C" void kernel_launch(void* const* d_in, const int* in_sizes, int n_in,
                              void* d_out, int out_size) {
    const float* x = (const float*)d_in[0];   // [256, 8, 1152]
    const float* W = (const float*)d_in[1];   // [1, 1152, 10, 16, 8]
    float* out = (float*)d_out;               // [1152, 10, 16]

    mono_kernel<<<NBLK, NTHR>>>(x, W, out);
}

// round 14
// speedup vs baseline: 1.2362x; 1.2362x over previous
#include <cuda_runtime.h>

#define NBLK 144   // 8 capsules per block
#define NTHR 640   // 2 elements per thread (capsules lc and lc+4, same (u,s))

__global__ void __launch_bounds__(NTHR) mono_kernel(const float* __restrict__ x,
                                                    const float* __restrict__ W,
                                                    float* __restrict__ out) {
    const int t = threadIdx.x;            // 0..639
    const int blk = blockIdx.x;           // 0..143  -> capsules blk*8 .. blk*8+7

    __shared__ float4 sm4[512];           // stage-1 partials  [bg*16 + ih]
    __shared__ float4 sm4b[128];          // stage-2 partials  [g*16 + ih]
    __shared__ float sm_xs[64];           // xs[i*8 + c_local]
    __shared__ float sm_usq[80];          // per (lc,u)
    __shared__ float sm_b[80];
    __shared__ float sm_e[80];
    __shared__ float sm_k[80];

    // ── W stream first: 4 coalesced LDG.128 per thread (both elements) ──
    const size_t e0 = (size_t)blk * 1280 + t;
    const size_t e1 = e0 + 640;
    const float4* w4 = reinterpret_cast<const float4*>(W);
    const float4 wA0 = __ldg(w4 + e0 * 2);
    const float4 wA1 = __ldg(w4 + e0 * 2 + 1);
    const float4 wB0 = __ldg(w4 + e1 * 2);
    const float4 wB1 = __ldg(w4 + e1 * 2 + 1);

    // ── x gather: this block's 8 capsule columns, full 32B sectors ──
    // x as float4: [b][i][q], q = c/4; this block owns q = blk*2 + {0,1}.
    // t<512: ih = i*2+half (16), bg = batch-group (32); 8 loads, MLP=8.
    if (t < 512) {
        const int ih = t & 15;
        const int i = ih >> 1;
        const int half = ih & 1;
        const int bg = t >> 4;            // 0..31, 8 batches each
        const float4* p = reinterpret_cast<const float4*>(x)
                        + (size_t)(bg * 8) * 2304 + i * 288 + blk * 2 + half;
        const float4 v0 = __ldg(p);
        const float4 v1 = __ldg(p + 2304);
        const float4 v2 = __ldg(p + 2 * 2304);
        const float4 v3 = __ldg(p + 3 * 2304);
        const float4 v4 = __ldg(p + 4 * 2304);
        const float4 v5 = __ldg(p + 5 * 2304);
        const float4 v6 = __ldg(p + 6 * 2304);
        const float4 v7 = __ldg(p + 7 * 2304);
        float4 a;
        a.x = ((v0.x + v1.x) + (v2.x + v3.x)) + ((v4.x + v5.x) + (v6.x + v7.x));
        a.y = ((v0.y + v1.y) + (v2.y + v3.y)) + ((v4.y + v5.y) + (v6.y + v7.y));
        a.z = ((v0.z + v1.z) + (v2.z + v3.z)) + ((v4.z + v5.z) + (v6.z + v7.z));
        a.w = ((v0.w + v1.w) + (v2.w + v3.w)) + ((v4.w + v5.w) + (v6.w + v7.w));
        sm4[t] = a;                       // [bg*16 + ih]
    }
    __syncthreads();
    if (t < 128) {                        // sum 4 bg's -> [g*16 + ih], g=0..7
        const int ih = t & 15;
        const int g = t >> 4;
        const float4 s0 = sm4[(g * 4 + 0) * 16 + ih];
        const float4 s1 = sm4[(g * 4 + 1) * 16 + ih];
        const float4 s2 = sm4[(g * 4 + 2) * 16 + ih];
        const float4 s3 = sm4[(g * 4 + 3) * 16 + ih];
        float4 a;
        a.x = (s0.x + s1.x) + (s2.x + s3.x);
        a.y = (s0.y + s1.y) + (s2.y + s3.y);
        a.z = (s0.z + s1.z) + (s2.z + s3.z);
        a.w = (s0.w + s1.w) + (s2.w + s3.w);
        sm4b[g * 16 + ih] = a;
    }
    __syncthreads();
    if (t < 16) {                         // final 8-way sum -> xs scalars
        const int ih = t;
        float4 a = sm4b[ih];
        #pragma unroll
        for (int g = 1; g < 8; ++g) {
            const float4 s = sm4b[g * 16 + ih];
            a.x += s.x; a.y += s.y; a.z += s.z; a.w += s.w;
        }
        const int i = ih >> 1;
        const int half = ih & 1;
        sm_xs[i * 8 + half * 4 + 0] = a.x;
        sm_xs[i * 8 + half * 4 + 1] = a.y;
        sm_xs[i * 8 + half * 4 + 2] = a.z;
        sm_xs[i * 8 + half * 4 + 3] = a.w;
    }
    __syncthreads();

    // ── us for both elements; warps never straddle lc (160 = 5 warps) ──
    const int lc0 = t / 160;              // 0..3 ; element 1 is capsule lc0+4
    const int r = t - lc0 * 160;          // u*16 + s
    const int u = r >> 4;

    const float usA = wA0.x * sm_xs[0 * 8 + lc0] + wA0.y * sm_xs[1 * 8 + lc0]
                    + wA0.z * sm_xs[2 * 8 + lc0] + wA0.w * sm_xs[3 * 8 + lc0]
                    + wA1.x * sm_xs[4 * 8 + lc0] + wA1.y * sm_xs[5 * 8 + lc0]
                    + wA1.z * sm_xs[6 * 8 + lc0] + wA1.w * sm_xs[7 * 8 + lc0];
    const int lc1 = lc0 + 4;
    const float usB = wB0.x * sm_xs[0 * 8 + lc1] + wB0.y * sm_xs[1 * 8 + lc1]
                    + wB0.z * sm_xs[2 * 8 + lc1] + wB0.w * sm_xs[3 * 8 + lc1]
                    + wB1.x * sm_xs[4 * 8 + lc1] + wB1.y * sm_xs[5 * 8 + lc1]
                    + wB1.z * sm_xs[6 * 8 + lc1] + wB1.w * sm_xs[7 * 8 + lc1];

    // ||u_sum||^2 over the 16 s-lanes of each (c,u) group
    float qA = usA * usA, qB = usB * usB;
    #pragma unroll
    for (int off = 8; off; off >>= 1) {
        qA += __shfl_xor_sync(0xffffffffu, qA, off);
        qB += __shfl_xor_sync(0xffffffffu, qB, off);
    }
    if ((t & 15) == 0) {
        sm_usq[lc0 * 10 + u] = qA;
        sm_usq[lc1 * 10 + u] = qB;
    }
    __syncthreads();

    // ── Scalar routing on t<80 (t = cc*10 + uu); MUFU confined to 80 thr ──
    {
        const bool act = (t < 80);
        const int cc = act ? (t / 10) : 0;
        const float usq = act ? sm_usq[t] : 0.f;
        float b = 0.f, cij = 0.1f, k = 0.f;   // softmax(0) = 1/10 exact

        #pragma unroll
        for (int it = 0; it < 3; ++it) {
            if (act) {
                const float msq = cij * cij * usq;
                const float coef = msq / (1.0f + msq) * rsqrtf(msq);
                k = coef * cij;
                if (it < 2) { b += k * usq * (1.0f / 256.0f); sm_b[t] = b; }
            }
            if (it < 2) {
                __syncthreads();
                float ex = 0.f;
                if (act) {
                    const float* bb = sm_b + cc * 10;
                    float m = bb[0];
                    #pragma unroll
                    for (int j = 1; j < 10; ++j) m = fmaxf(m, bb[j]);
                    ex = __expf(b - m);
                    sm_e[t] = ex;
                }
                __syncthreads();
                if (act) {
                    const float* ep = sm_e + cc * 10;
                    float d = ep[0];
                    #pragma unroll
                    for (int j = 1; j < 10; ++j) d += ep[j];
                    cij = ex / d;
                }
            }
        }
        if (act) sm_k[t] = k;
    }
    __syncthreads();

    // ── Final scale; coalesced stores ──
    out[e0] = sm_k[lc0 * 10 + u] * usA;
    out[e1] = sm_k[lc1 * 10 + u] * usB;
}

extern "C" void kernel_launch(void* const* d_in, const int* in_sizes, int n_in,
                              void* d_out, int out_size) {
    const float* x = (const float*)d_in[0];   // [256, 8, 1152]
    const float* W = (const float*)d_in[1];   // [1, 1152, 10, 16, 8]
    float* out = (float*)d_out;               // [1152, 10, 16]

    mono_kernel<<<NBLK, NTHR>>>(x, W, out);
}

// round 15
// speedup vs baseline: 1.2407x; 1.0037x over previous
#include <cuda_runtime.h>

#define NTHR 320

__device__ __forceinline__ unsigned cta_rank() {
    unsigned r;
    asm("mov.u32 %0, %%cluster_ctarank;" : "=r"(r));
    return r;
}

// Cluster of 2 CTAs per 8-capsule group. CTA rank reduces batch half `rank`
// (full 32B x sectors) and owns 4 capsules end-to-end. Partial xs exchanged
// via DSMEM after one cluster barrier; everything else is CTA-local.
__global__ void __launch_bounds__(NTHR) __cluster_dims__(2, 1, 1)
mono_kernel(const float* __restrict__ x, const float* __restrict__ W,
            float* __restrict__ out) {
    const int t = threadIdx.x;             // 0..319
    const int cg = blockIdx.x >> 1;        // 0..143, capsules cg*8..cg*8+7
    const unsigned bh = cta_rank();        // batch half 0/1; also capsule half

    __shared__ float4 sm4[256];            // [bg*16 + ih]
    __shared__ float4 sm4b[128];           // [g*16 + ih]
    __shared__ float sm_xsp[64];           // my partial xs [i*8 + clocal]
    __shared__ float sm_xs[64];            // full xs
    __shared__ float sm_usq[40];
    __shared__ float sm_b[40];
    __shared__ float sm_e[40];
    __shared__ float sm_k[40];

    // ── W stream first: this CTA's 640 elements (2 per thread), coalesced ──
    const size_t base = ((size_t)cg * 8 + bh * 4) * 160;
    const size_t e0 = base + t;
    const size_t e1 = e0 + 320;
    const float4* w4 = reinterpret_cast<const float4*>(W);
    const float4 wA0 = __ldg(w4 + e0 * 2);
    const float4 wA1 = __ldg(w4 + e0 * 2 + 1);
    const float4 wB0 = __ldg(w4 + e1 * 2);
    const float4 wB1 = __ldg(w4 + e1 * 2 + 1);

    // ── x gather: batches bh*128..+128, all 8 capsules (full 32B sectors) ──
    // x as float4 [b][i][q]; this group owns q = cg*2 + half.
    if (t < 256) {
        const int ih = t & 15;             // i*2 + half
        const int i = ih >> 1;
        const int half = ih & 1;
        const int bg = t >> 4;             // 16 groups of 8 batches
        const float4* p = reinterpret_cast<const float4*>(x)
                        + (size_t)(bh * 128 + bg * 8) * 2304 + i * 288 + cg * 2 + half;
        const float4 v0 = __ldg(p);
        const float4 v1 = __ldg(p + 2304);
        const float4 v2 = __ldg(p + 2 * 2304);
        const float4 v3 = __ldg(p + 3 * 2304);
        const float4 v4 = __ldg(p + 4 * 2304);
        const float4 v5 = __ldg(p + 5 * 2304);
        const float4 v6 = __ldg(p + 6 * 2304);
        const float4 v7 = __ldg(p + 7 * 2304);
        float4 a;
        a.x = ((v0.x + v1.x) + (v2.x + v3.x)) + ((v4.x + v5.x) + (v6.x + v7.x));
        a.y = ((v0.y + v1.y) + (v2.y + v3.y)) + ((v4.y + v5.y) + (v6.y + v7.y));
        a.z = ((v0.z + v1.z) + (v2.z + v3.z)) + ((v4.z + v5.z) + (v6.z + v7.z));
        a.w = ((v0.w + v1.w) + (v2.w + v3.w)) + ((v4.w + v5.w) + (v6.w + v7.w));
        sm4[t] = a;
    }
    __syncthreads();
    if (t < 128) {                         // 16 bg -> 8
        const int ih = t & 15;
        const int g = t >> 4;
        const float4 s0 = sm4[(2 * g) * 16 + ih];
        const float4 s1 = sm4[(2 * g + 1) * 16 + ih];
        float4 a;
        a.x = s0.x + s1.x; a.y = s0.y + s1.y;
        a.z = s0.z + s1.z; a.w = s0.w + s1.w;
        sm4b[g * 16 + ih] = a;
    }
    __syncthreads();
    if (t < 16) {                          // 8 -> 1; scatter to scalar layout
        const int ih = t;
        float4 a = sm4b[ih];
        #pragma unroll
        for (int g = 1; g < 8; ++g) {
            const float4 s = sm4b[g * 16 + ih];
            a.x += s.x; a.y += s.y; a.z += s.z; a.w += s.w;
        }
        const int i = ih >> 1;
        const int half = ih & 1;
        sm_xsp[i * 8 + half * 4 + 0] = a.x;
        sm_xsp[i * 8 + half * 4 + 1] = a.y;
        sm_xsp[i * 8 + half * 4 + 2] = a.z;
        sm_xsp[i * 8 + half * 4 + 3] = a.w;
    }

    // ── Exchange partial xs with peer CTA via DSMEM ──
    asm volatile("barrier.cluster.arrive.aligned;" ::: "memory");
    asm volatile("barrier.cluster.wait.aligned;" ::: "memory");

    if (t < 64) {
        const unsigned my = (unsigned)__cvta_generic_to_shared(&sm_xsp[t]);
        unsigned peer;
        asm("mapa.shared::cluster.u32 %0, %1, %2;" : "=r"(peer) : "r"(my), "r"(bh ^ 1u));
        float pv;
        asm volatile("ld.shared::cluster.f32 %0, [%1];" : "=f"(pv) : "r"(peer));
        // fixed order: half0 + half1 (identical on both CTAs -> deterministic)
        const float mine = sm_xsp[t];
        sm_xs[t] = bh ? (pv + mine) : (mine + pv);
    }
    __syncthreads();

    // ── us for both elements; caps owned: bh*4 + {0..3} (xs index abs) ──
    const int lc0 = t / 160;               // 0..1
    const int r = t - lc0 * 160;
    const int u = r >> 4;
    const int ca = (int)bh * 4 + lc0;      // abs cap-in-group for element A
    const int cb = ca + 2;                 // for element B

    const float usA = wA0.x * sm_xs[0 * 8 + ca] + wA0.y * sm_xs[1 * 8 + ca]
                    + wA0.z * sm_xs[2 * 8 + ca] + wA0.w * sm_xs[3 * 8 + ca]
                    + wA1.x * sm_xs[4 * 8 + ca] + wA1.y * sm_xs[5 * 8 + ca]
                    + wA1.z * sm_xs[6 * 8 + ca] + wA1.w * sm_xs[7 * 8 + ca];
    const float usB = wB0.x * sm_xs[0 * 8 + cb] + wB0.y * sm_xs[1 * 8 + cb]
                    + wB0.z * sm_xs[2 * 8 + cb] + wB0.w * sm_xs[3 * 8 + cb]
                    + wB1.x * sm_xs[4 * 8 + cb] + wB1.y * sm_xs[5 * 8 + cb]
                    + wB1.z * sm_xs[6 * 8 + cb] + wB1.w * sm_xs[7 * 8 + cb];

    // ||u_sum||^2 over the 16 s-lanes (groups 16-aligned: 160 ≡ 0 mod 16)
    float qA = usA * usA, qB = usB * usB;
    #pragma unroll
    for (int off = 8; off; off >>= 1) {
        qA += __shfl_xor_sync(0xffffffffu, qA, off);
        qB += __shfl_xor_sync(0xffffffffu, qB, off);
    }
    if ((t & 15) == 0) {
        sm_usq[lc0 * 10 + u] = qA;          // block-local caps 0..1
        sm_usq[(lc0 + 2) * 10 + u] = qB;    // block-local caps 2..3
    }
    __syncthreads();

    // ── Scalar routing on t<40 (t = cc*10 + uu) ──
    {
        const bool act = (t < 40);
        const int cc = act ? (t / 10) : 0;
        const float usq = act ? sm_usq[t] : 0.f;
        float b = 0.f, cij = 0.1f, k = 0.f;   // softmax(0) = 1/10 exact

        #pragma unroll
        for (int it = 0; it < 3; ++it) {
            if (act) {
                const float msq = cij * cij * usq;
                const float coef = msq / (1.0f + msq) * rsqrtf(msq);
                k = coef * cij;
                if (it < 2) { b += k * usq * (1.0f / 256.0f); sm_b[t] = b; }
            }
            if (it < 2) {
                __syncthreads();
                float ex = 0.f;
                if (act) {
                    const float* bb = sm_b + cc * 10;
                    float m = bb[0];
                    #pragma unroll
                    for (int j = 1; j < 10; ++j) m = fmaxf(m, bb[j]);
                    ex = __expf(b - m);
                    sm_e[t] = ex;
                }
                __syncthreads();
                if (act) {
                    const float* ep = sm_e + cc * 10;
                    float d = ep[0];
                    #pragma unroll
                    for (int j = 1; j < 10; ++j) d += ep[j];
                    cij = ex / d;
                }
            }
        }
        if (act) sm_k[t] = k;
    }
    __syncthreads();

    // ── Final scale; coalesced stores ──
    out[e0] = sm_k[lc0 * 10 + u] * usA;
    out[e1] = sm_k[(lc0 + 2) * 10 + u] * usB;

    // Keep smem alive until peer's DSMEM read is done.
    asm volatile("barrier.cluster.arrive.aligned;" ::: "memory");
    asm volatile("barrier.cluster.wait.aligned;" ::: "memory");
}

extern "C" void kernel_launch(void* const* d_in, const int* in_sizes, int n_in,
                              void* d_out, int out_size) {
    const float* x = (const float*)d_in[0];   // [256, 8, 1152]
    const float* W = (const float*)d_in[1];   // [1, 1152, 10, 16, 8]
    float* out = (float*)d_out;               // [1152, 10, 16]

    cudaLaunchConfig_t cfg = {};
    cfg.gridDim = dim3(288);
    cfg.blockDim = dim3(NTHR);
    cfg.dynamicSmemBytes = 0;
    cfg.stream = 0;
    cudaLaunchAttribute attr[1];
    attr[0].id = cudaLaunchAttributeClusterDimension;
    attr[0].val.clusterDim = {2, 1, 1};
    cfg.attrs = attr;
    cfg.numAttrs = 1;
    cudaLaunchKernelEx(&cfg, mono_kernel, x, W, out);
}